// round 1
// baseline (speedup 1.0000x reference)
#include <cuda_runtime.h>

#define HH 256
#define WW 256
#define PP 512
// ALPHA = -5.0f, 1/ALPHA = -0.2f

__device__ float g_maxd;
__device__ float g_partB[HH * PP];   // per-row partial soft sums (256 * 512 floats = 512KB)
__device__ float g_numA[HH];
__device__ float g_denA[HH];

__device__ __forceinline__ float frcp_a(float x) {
    float r; asm("rcp.approx.f32 %0, %1;" : "=f"(r) : "f"(x)); return r;
}
__device__ __forceinline__ float frsqrt_a(float x) {
    float r; asm("rsqrt.approx.f32 %0, %1;" : "=f"(r) : "f"(x)); return r;
}

// ---------------------------------------------------------------------------
// K1: global max distance. Max over the discrete grid is attained at a corner
// per coordinate: max_y (y-py)^2 = max(py, 255-py)^2, same for x.
// ---------------------------------------------------------------------------
__global__ void k_maxd(const float* __restrict__ pts) {
    int j = threadIdx.x;                       // 512 threads = 512 points
    float py = pts[2 * j], px = pts[2 * j + 1];
    float my = fmaxf(py, (float)(HH - 1) - py);
    float mx = fmaxf(px, (float)(WW - 1) - px);
    float s = my * my + mx * mx;
    __shared__ float sm[PP];
    sm[j] = s;
    __syncthreads();
    for (int off = 256; off > 0; off >>= 1) {
        if (j < off) sm[j] = fmaxf(sm[j], sm[j + off]);
        __syncthreads();
    }
    if (j == 0) g_maxd = sqrtf(sm[0]);
}

// ---------------------------------------------------------------------------
// K2: per-pixel min squared distance + term-1 partials (one block per row).
// dx^2 depends only on (row, point) -> precompute per block into smem.
// ---------------------------------------------------------------------------
__global__ void k_min(const float* __restrict__ hm, const float* __restrict__ pts) {
    __shared__ float2 pre[PP];                 // (px, dx*dx) per point for this row
    int x = threadIdx.x;                       // 256 threads = columns
    int y = blockIdx.x;                        // 256 blocks  = rows
    float yf = (float)y;

    for (int j = x; j < PP; j += 256) {
        float py = pts[2 * j], px = pts[2 * j + 1];
        float dx = yf - py;
        pre[j] = make_float2(px, dx * dx);
    }
    __syncthreads();

    float xf = (float)x;
    float mins = 3.4e38f;
#pragma unroll 8
    for (int j = 0; j < PP; ++j) {
        float2 pp = pre[j];
        float dy = xf - pp.x;
        float s = fmaf(dy, dy, pp.y);
        mins = fminf(mins, s);
    }

    float h = hm[y * WW + x];
    float t1 = h * sqrtf(mins);
    float ah = fabsf(h);

    // deterministic block reduction: warp shuffles + fixed-order smem combine
    for (int o = 16; o > 0; o >>= 1) {
        t1 += __shfl_down_sync(0xffffffffu, t1, o);
        ah += __shfl_down_sync(0xffffffffu, ah, o);
    }
    __shared__ float w1[8], w2[8];
    int warp = x >> 5, lane = x & 31;
    if (lane == 0) { w1[warp] = t1; w2[warp] = ah; }
    __syncthreads();
    if (x == 0) {
        float a = 0.f, b = 0.f;
#pragma unroll
        for (int i = 0; i < 8; ++i) { a += w1[i]; b += w2[i]; }
        g_numA[y] = a;
        g_denA[y] = b;
    }
}

// ---------------------------------------------------------------------------
// K3: soft-min power sums. One block per row; 256 threads; each thread owns
// 2 points and loops over the row's 256 pixels with incremental dy.
// Accumulates S_j = sum_pixels w^-5 into registers, writes per-row partials.
// ---------------------------------------------------------------------------
__global__ void k_soft(const float* __restrict__ hm, const float* __restrict__ pts) {
    __shared__ float s_hm[WW];
    int tid = threadIdx.x;                     // 256
    int y = blockIdx.x;                        // 256 rows
    s_hm[tid] = hm[y * WW + tid];

    float M = g_maxd;
    int j0 = tid, j1 = tid + 256;
    float py0 = pts[2 * j0], px0 = pts[2 * j0 + 1];
    float py1 = pts[2 * j1], px1 = pts[2 * j1 + 1];

    float yf = (float)y;
    float dx0 = yf - py0, dx1 = yf - py1;
    float dxs0 = dx0 * dx0, dxs1 = dx1 * dx1;
    float dy0 = -px0 - 1.0f;                   // pre-decremented; +1 at loop head
    float dy1 = -px1 - 1.0f;
    float S0 = 0.f, S1 = 0.f;
    __syncthreads();

#pragma unroll 4
    for (int x = 0; x < WW; ++x) {
        float h = s_hm[x];
        float b = fmaf(-h, M, M);              // (1-h)*M
        dy0 += 1.0f;
        dy1 += 1.0f;
        float s0 = fmaf(dy0, dy0, dxs0);
        float s1 = fmaf(dy1, dy1, dxs1);
        float r0 = frsqrt_a(s0);
        float r1 = frsqrt_a(s1);
        float d0 = s0 * r0;                    // sqrt(s) = s * rsqrt(s)
        float d1 = s1 * r1;
        float w0 = fmaf(h, d0, b);
        float w1 = fmaf(h, d1, b);
        float q0 = frcp_a(w0);
        float q1 = frcp_a(w1);
        float q02 = q0 * q0, q12 = q1 * q1;
        float q04 = q02 * q02, q14 = q12 * q12;
        S0 = fmaf(q04, q0, S0);                // += q^5
        S1 = fmaf(q14, q1, S1);
    }
    g_partB[y * PP + j0] = S0;
    g_partB[y * PP + j1] = S1;
}

// ---------------------------------------------------------------------------
// K4: finalize. Deterministic reductions over partials, powf, combine.
// ---------------------------------------------------------------------------
__global__ void k_final(float* __restrict__ out) {
    int j = threadIdx.x;                       // 512 threads
    float S = 0.f;
    for (int y = 0; y < HH; ++y) S += g_partB[y * PP + j];
    float smv = powf(S * (1.0f / (HH * WW)), -0.2f);   // (mean)^(1/ALPHA)

    __shared__ float red[PP];
    red[j] = smv;
    __syncthreads();
    for (int off = 256; off > 0; off >>= 1) {
        if (j < off) red[j] += red[j + off];
        __syncthreads();
    }

    __shared__ float r2[HH], r3[HH];
    if (j < HH) { r2[j] = g_numA[j]; r3[j] = g_denA[j]; }
    __syncthreads();
    for (int off = 128; off > 0; off >>= 1) {
        if (j < off) { r2[j] += r2[j + off]; r3[j] += r3[j + off]; }
        __syncthreads();
    }

    if (j == 0) {
        float mean_soft_min = red[0] * (1.0f / PP);
        float term1 = r2[0] / r3[0];
        out[0] = term1 + mean_soft_min;
    }
}

extern "C" void kernel_launch(void* const* d_in, const int* in_sizes, int n_in,
                              void* d_out, int out_size) {
    (void)in_sizes; (void)n_in; (void)out_size;
    const float* hm  = (const float*)d_in[0];   // heat_map (256*256)
    const float* pts = (const float*)d_in[1];   // points   (512*2)
    float* out = (float*)d_out;

    k_maxd<<<1, 512>>>(pts);
    k_min<<<HH, 256>>>(hm, pts);
    k_soft<<<HH, 256>>>(hm, pts);
    k_final<<<1, 512>>>(out);
}